// round 1
// baseline (speedup 1.0000x reference)
#include <cuda_runtime.h>
#include <cuda_bf16.h>

#define Mdim 2048
#define Ndim 4096
#define COLS 28          // columns of A owned per block
#define NB   147         // ceil(4096/28); last block owns 8 cols
#define NT   256
#define NWARP 8
#define OUTER_IT 100
#define INNER_IT 20
#define RHO_C  1.0f
#define STEP_C 5e-5f
#define ROWS_PER_B 14    // 147*14 = 2058 >= 2048 row-ownership for resets/epilogue

// Global state (device globals: no allocation allowed)
__device__ float g_ybuf[3][Mdim];   // rotating Ax accumulators
__device__ float g_r[Mdim];
__device__ float g_s[Mdim];
__device__ float g_u[Mdim];
__device__ unsigned g_bar_count;    // zero-init; returns to 0 after each barrier
__device__ unsigned g_bar_gen;

__device__ __forceinline__ void grid_bar() {
    __threadfence();
    __syncthreads();
    if (threadIdx.x == 0) {
        unsigned gen = *((volatile unsigned*)&g_bar_gen);
        if (atomicAdd(&g_bar_count, 1u) == (unsigned)(NB - 1)) {
            g_bar_count = 0u;
            __threadfence();
            atomicExch(&g_bar_gen, gen + 1u);
        } else {
            while (*((volatile unsigned*)&g_bar_gen) == gen) __nanosleep(32);
        }
    }
    __syncthreads();
}

extern "C" __global__ void __launch_bounds__(NT, 1)
admm_persistent(const float* __restrict__ A,
                const float* __restrict__ b,
                const float* __restrict__ c,
                float* __restrict__ out)
{
    extern __shared__ float sm[];
    float* As  = sm;                      // COLS * Mdim floats, column-major slice of A
    float* xs  = sm + COLS * Mdim;        // 32 floats (x chunk)
    float* cs  = xs + 32;                 // 32 floats (c chunk)
    float* red = cs + 32;                 // COLS * NWARP reduction scratch

    const int tid  = threadIdx.x;
    const int w    = tid >> 5;
    const int lane = tid & 31;
    const int bid  = blockIdx.x;
    const int j0   = bid * COLS;
    const int myCols = (Ndim - j0) < COLS ? (Ndim - j0) : COLS;

    // ---- startup: load A column slice into SMEM (zero-padded), init state ----
    for (int idx = tid; idx < COLS * Mdim; idx += NT) {
        int i  = idx / COLS;
        int jj = idx - i * COLS;
        As[jj * Mdim + i] = (jj < myCols) ? A[(size_t)i * Ndim + (j0 + jj)] : 0.0f;
    }
    if (tid < COLS) {
        xs[tid] = 0.0f;
        cs[tid] = (tid < myCols) ? c[j0 + tid] : 0.0f;
    }
    const int rb = bid * ROWS_PER_B;
    const int nr0 = Mdim - rb;
    const int nr  = nr0 < ROWS_PER_B ? (nr0 < 0 ? 0 : nr0) : ROWS_PER_B;
    for (int ii = tid; ii < nr; ii += NT) {
        int i = rb + ii;
        g_s[i] = 0.0f; g_u[i] = 0.0f; g_r[i] = b[i];   // r = s + b - u = b initially
        g_ybuf[0][i] = 0.0f; g_ybuf[1][i] = 0.0f; g_ybuf[2][i] = 0.0f;
    }
    grid_bar();

    const float4* As4 = (const float4*)As;
    const int g0 = w * 64 + lane;   // float4 row-group index (rows 4*g0..4*g0+3)
    const int g1 = g0 + 32;

    int bsel = 0;
    for (int outer = 0; outer < OUTER_IT; ++outer) {
        for (int step = 0; step <= INNER_IT; ++step) {
            // ---------------- phase A: partial Ax, reduce into g_ybuf[bsel] ---------
            {
                float* yb = g_ybuf[bsel];
                float xr[COLS];
#pragma unroll
                for (int j = 0; j < COLS; ++j) xr[j] = xs[j];
                float4 a0 = make_float4(0.f, 0.f, 0.f, 0.f);
                float4 a1 = make_float4(0.f, 0.f, 0.f, 0.f);
#pragma unroll
                for (int j = 0; j < COLS; ++j) {
                    float4 v0 = As4[j * (Mdim / 4) + g0];
                    float4 v1 = As4[j * (Mdim / 4) + g1];
                    float xv = xr[j];
                    a0.x = fmaf(v0.x, xv, a0.x);
                    a0.y = fmaf(v0.y, xv, a0.y);
                    a0.z = fmaf(v0.z, xv, a0.z);
                    a0.w = fmaf(v0.w, xv, a0.w);
                    a1.x = fmaf(v1.x, xv, a1.x);
                    a1.y = fmaf(v1.y, xv, a1.y);
                    a1.z = fmaf(v1.z, xv, a1.z);
                    a1.w = fmaf(v1.w, xv, a1.w);
                }
                atomicAdd(&yb[4 * g0 + 0], a0.x);
                atomicAdd(&yb[4 * g0 + 1], a0.y);
                atomicAdd(&yb[4 * g0 + 2], a0.z);
                atomicAdd(&yb[4 * g0 + 3], a0.w);
                atomicAdd(&yb[4 * g1 + 0], a1.x);
                atomicAdd(&yb[4 * g1 + 1], a1.y);
                atomicAdd(&yb[4 * g1 + 2], a1.z);
                atomicAdd(&yb[4 * g1 + 3], a1.w);
            }
            grid_bar();   // the ONLY grid sync per iteration

            const float* yb = g_ybuf[bsel];
            float* zb = g_ybuf[bsel >= 1 ? bsel - 1 : 2];   // (bsel+2)%3: reset target

            if (step < INNER_IT) {
                // ------------- phase B: g = c + rho*A^T(Ax - r); x = max(x-step*g,0)
                float4 y0 = __ldcg((const float4*)yb + g0);
                float4 r0 = __ldcg((const float4*)g_r + g0);
                float4 y1 = __ldcg((const float4*)yb + g1);
                float4 r1 = __ldcg((const float4*)g_r + g1);
                float4 e0 = make_float4(y0.x - r0.x, y0.y - r0.y, y0.z - r0.z, y0.w - r0.w);
                float4 e1 = make_float4(y1.x - r1.x, y1.y - r1.y, y1.z - r1.z, y1.w - r1.w);
                float acc[COLS];
#pragma unroll
                for (int j = 0; j < COLS; ++j) {
                    float4 v0 = As4[j * (Mdim / 4) + g0];
                    float4 v1 = As4[j * (Mdim / 4) + g1];
                    float s = v0.x * e0.x;
                    s = fmaf(v0.y, e0.y, s);
                    s = fmaf(v0.z, e0.z, s);
                    s = fmaf(v0.w, e0.w, s);
                    s = fmaf(v1.x, e1.x, s);
                    s = fmaf(v1.y, e1.y, s);
                    s = fmaf(v1.z, e1.z, s);
                    s = fmaf(v1.w, e1.w, s);
                    acc[j] = s;
                }
#pragma unroll
                for (int j = 0; j < COLS; ++j) {
                    float v = acc[j];
                    v += __shfl_xor_sync(0xffffffffu, v, 16);
                    v += __shfl_xor_sync(0xffffffffu, v, 8);
                    v += __shfl_xor_sync(0xffffffffu, v, 4);
                    v += __shfl_xor_sync(0xffffffffu, v, 2);
                    v += __shfl_xor_sync(0xffffffffu, v, 1);
                    if (lane == 0) red[j * NWARP + w] = v;
                }
                // reset the buffer that will be accumulated 2 iterations from now
                for (int ii = tid; ii < nr; ii += NT) zb[rb + ii] = 0.0f;
                __syncthreads();
                if (tid < myCols) {
                    float g = 0.0f;
#pragma unroll
                    for (int ww = 0; ww < NWARP; ++ww) g += red[tid * NWARP + ww];
                    float xn = xs[tid] - STEP_C * (cs[tid] + RHO_C * g);
                    xs[tid] = fmaxf(xn, 0.0f);
                }
                __syncthreads();
            } else {
                // ------------- epilogue: s, u, r updates (row-owned) ---------------
                for (int ii = tid; ii < nr; ii += NT) {
                    int i = rb + ii;
                    float Ax = __ldcg(&yb[i]);
                    float bi = b[i];
                    float ui = g_u[i];
                    float sn = fmaxf(Ax - bi + ui, 0.0f);
                    float un = ui + (Ax - sn - bi);
                    g_s[i] = sn;
                    g_u[i] = un;
                    g_r[i] = sn + bi - un;
                    zb[i] = 0.0f;
                    if (outer == OUTER_IT - 1) {
                        out[Ndim + i]            = sn;          // s
                        out[Ndim + Mdim + i]     = un;          // u
                        out[Ndim + 2 * Mdim + i] = -RHO_C * un; // lambda_kkt
                    }
                }
            }
            bsel = (bsel + 1 == 3) ? 0 : bsel + 1;
        }
    }
    // final x (block-local, no sync needed)
    if (tid < myCols) out[j0 + tid] = xs[tid];
}

extern "C" void kernel_launch(void* const* d_in, const int* in_sizes, int n_in,
                              void* d_out, int out_size) {
    const float* A = nullptr;
    const float* b = nullptr;
    const float* c = nullptr;
    for (int k = 0; k < n_in; ++k) {
        if (in_sizes[k] == Mdim * Ndim)      A = (const float*)d_in[k];
        else if (in_sizes[k] == Mdim)        b = (const float*)d_in[k];
        else if (in_sizes[k] == Ndim)        c = (const float*)d_in[k];
    }
    float* out = (float*)d_out;
    size_t shmem = (size_t)(COLS * Mdim + 32 + 32 + COLS * NWARP) * sizeof(float); // 230,528 B
    cudaFuncSetAttribute(admm_persistent,
                         cudaFuncAttributeMaxDynamicSharedMemorySize, (int)shmem);
    admm_persistent<<<NB, NT, shmem>>>(A, b, c, out);
}